// round 2
// baseline (speedup 1.0000x reference)
#include <cuda_runtime.h>
#include <cuda_bf16.h>
#include <math.h>

// ---------------------------------------------------------------------------
// Problem constants (Mamba2 block)
// ---------------------------------------------------------------------------
#define BATCH     2
#define SEQLEN    4096
#define DMODEL    1024
#define DSTATE    128
#define DCONV     4
#define HEADDIM   64
#define DINNER    2048
#define NHEADS    32
#define CONVDIM   2304              // DINNER + 2*DSTATE
#define DINPROJ   4384              // 2*DINNER + 2*DSTATE + NHEADS
#define ROWS      (BATCH*SEQLEN)    // 8192
#define DTCOL     (2*DINNER + 2*DSTATE)   // 4352: dt column base in zxbcdt

// Scratch buffers (allocation-free rule: __device__ globals)
__device__ float g_zxbcdt[(size_t)ROWS * DINPROJ];   // in_proj output
__device__ float g_conv  [(size_t)ROWS * CONVDIM];   // conv+silu output
__device__ float g_y     [(size_t)ROWS * DINNER];    // scan output -> gated/normed in place

// ---------------------------------------------------------------------------
// SGEMM: C[M,N] = A[M,K] * B[K,N], row-major fp32.
// 128x128 tile, BK=8, 256 threads, 8x8 microtile. N guarded (4384 case).
// ---------------------------------------------------------------------------
__global__ __launch_bounds__(256, 2)
void sgemm_kernel(const float* __restrict__ A, const float* __restrict__ B,
                  float* __restrict__ C, int M, int N, int K)
{
    const int BM = 128, BN = 128, BK = 8, TM = 8, TN = 8;
    __shared__ float As[BK][BM];
    __shared__ float Bs[BK][BN];

    int tid  = threadIdx.x;
    int rowC = blockIdx.y * BM;
    int colC = blockIdx.x * BN;

    int tx = tid % 16;            // N direction
    int ty = tid / 16;            // M direction

    int aRow = tid >> 1;          // 0..127
    int aCol = (tid & 1) * 4;     // 0 or 4
    int bRow = tid >> 5;          // 0..7
    int bCol = (tid & 31) * 4;    // 0..124

    const float* Abase = A + (size_t)rowC * K;
    float acc[TM][TN];
    #pragma unroll
    for (int i = 0; i < TM; i++)
        #pragma unroll
        for (int j = 0; j < TN; j++) acc[i][j] = 0.f;

    for (int k0 = 0; k0 < K; k0 += BK) {
        float4 av = *(const float4*)(Abase + (size_t)aRow * K + k0 + aCol);
        As[aCol + 0][aRow] = av.x;
        As[aCol + 1][aRow] = av.y;
        As[aCol + 2][aRow] = av.z;
        As[aCol + 3][aRow] = av.w;

        int gcol = colC + bCol;
        float4 bv = make_float4(0.f, 0.f, 0.f, 0.f);
        if (gcol < N)  // N % 4 == 0: float4 starting < N is fully in-bounds
            bv = *(const float4*)(B + (size_t)(k0 + bRow) * N + gcol);
        *(float4*)&Bs[bRow][bCol] = bv;

        __syncthreads();

        #pragma unroll
        for (int kk = 0; kk < BK; kk++) {
            float ar[TM], br[TN];
            #pragma unroll
            for (int i = 0; i < TM; i++) ar[i] = As[kk][ty * TM + i];
            #pragma unroll
            for (int j = 0; j < TN; j++) br[j] = Bs[kk][tx * TN + j];
            #pragma unroll
            for (int i = 0; i < TM; i++)
                #pragma unroll
                for (int j = 0; j < TN; j++)
                    acc[i][j] = fmaf(ar[i], br[j], acc[i][j]);
        }
        __syncthreads();
    }

    #pragma unroll
    for (int i = 0; i < TM; i++) {
        int r = rowC + ty * TM + i;
        #pragma unroll
        for (int j = 0; j < TN; j++) {
            int c = colC + tx * TN + j;
            if (c < N) C[(size_t)r * N + c] = acc[i][j];
        }
    }
}

// ---------------------------------------------------------------------------
// Causal depthwise conv1d (K=4) + SiLU on xBC slice of zxbcdt.
// ---------------------------------------------------------------------------
__global__ void conv_silu_kernel(const float* __restrict__ zxbcdt,
                                 const float* __restrict__ conv_w,
                                 const float* __restrict__ conv_b,
                                 float* __restrict__ out)
{
    long idx = (long)blockIdx.x * blockDim.x + threadIdx.x;
    const long total = (long)ROWS * CONVDIM;
    if (idx >= total) return;
    int  c = (int)(idx % CONVDIM);
    long r = idx / CONVDIM;
    int  l = (int)(r & (SEQLEN - 1));   // position within batch

    const float* xcol = zxbcdt + r * DINPROJ + DINNER + c;
    float acc = conv_b[c];
    #pragma unroll
    for (int j = 0; j < DCONV; j++) {
        if (l - j >= 0)
            acc = fmaf(conv_w[j * CONVDIM + c], xcol[-(long)j * DINPROJ], acc);
    }
    out[idx] = acc / (1.f + expf(-acc));   // silu
}

// ---------------------------------------------------------------------------
// Selective scan, p-split. One CTA per (b, h, p-quarter): 256 CTAs.
// 128 threads: pl = tid & 15 (local head-dim), nseg = tid >> 4 (16-wide n chunk).
// State s[pl][n0..n0+15] in 16 registers/thread.
// Double-buffered smem staging, ONE __syncthreads per timestep.
// Skip connection (+ x * D[h]) folded into the epilogue.
// ---------------------------------------------------------------------------
__global__ __launch_bounds__(128, 2)
void scan_kernel(const float* __restrict__ zxbcdt,
                 const float* __restrict__ convout,
                 const float* __restrict__ dt_bias,
                 const float* __restrict__ A_log,
                 const float* __restrict__ Dparam,
                 float* __restrict__ y)
{
    int bx  = blockIdx.x;
    int pq  = bx & 3;            // p-quarter 0..3
    int h   = (bx >> 2) & 31;    // head
    int b   = bx >> 7;           // batch
    int tid = threadIdx.x;
    int pl  = tid & 15;          // local p (0..15)
    int nseg = tid >> 4;         // 0..7
    int n0  = nseg * 16;

    const float A   = -expf(A_log[h]);
    const float dtb = dt_bias[h];
    const float Dh  = Dparam[h];
    const int   pcol = h * HEADDIM + pq * 16;   // x column base for this CTA

    float s[16];
    #pragma unroll
    for (int j = 0; j < 16; j++) s[j] = 0.f;

    __shared__ float sx [2][16];
    __shared__ float sB [2][DSTATE];
    __shared__ float sC [2][DSTATE];
    __shared__ float sdt[2];
    __shared__ float sdec[2];
    __shared__ float red[2][128];

    const long rowbase = (long)b * SEQLEN;

    // Prologue: stage t = 0 into buffer 0.
    {
        const float* crow = convout + rowbase * CONVDIM;
        if (tid < 16) sx[0][tid] = crow[pcol + tid];
        sB[0][tid] = crow[DINNER + tid];
        sC[0][tid] = crow[DINNER + DSTATE + tid];
        if (tid == 0) {
            float v  = zxbcdt[rowbase * DINPROJ + DTCOL + h] + dtb;
            float dt = (v > 20.f) ? v : log1pf(expf(v));
            sdt[0]  = dt;
            sdec[0] = expf(A * dt);
        }
    }
    __syncthreads();

    for (int t = 0; t < SEQLEN; t++) {
        int q = t & 1;

        // Prefetch t+1 into the other buffer (safe: its previous contents
        // were consumed before the sync at the end of iteration t-1).
        if (t + 1 < SEQLEN) {
            const float* crow = convout + (rowbase + t + 1) * CONVDIM;
            if (tid < 16) sx[q ^ 1][tid] = crow[pcol + tid];
            sB[q ^ 1][tid] = crow[DINNER + tid];
            sC[q ^ 1][tid] = crow[DINNER + DSTATE + tid];
            if (tid == 0) {
                float v  = zxbcdt[(rowbase + t + 1) * DINPROJ + DTCOL + h] + dtb;
                float dt = (v > 20.f) ? v : log1pf(expf(v));
                sdt[q ^ 1]  = dt;
                sdec[q ^ 1] = expf(A * dt);
            }
        }

        // Compute step t from buffer q.
        float dt  = sdt[q];
        float dec = sdec[q];
        float xv  = sx[q][pl];
        float xdt = xv * dt;
        float acc = 0.f;
        #pragma unroll
        for (int j = 0; j < 16; j++) {
            float sv = fmaf(s[j], dec, xdt * sB[q][n0 + j]);
            s[j] = sv;
            acc = fmaf(sv, sC[q][n0 + j], acc);
        }
        red[q][tid] = acc;
        __syncthreads();   // red[q] ready AND buffer q^1 fully staged

        if (nseg == 0) {
            float yv = xv * Dh;
            #pragma unroll
            for (int k = 0; k < 8; k++) yv += red[q][k * 16 + pl];
            y[(rowbase + t) * DINNER + pcol + pl] = yv;
        }
    }
}

// ---------------------------------------------------------------------------
// Gated RMSNorm in place on y:  g = y * silu(z);  g *= rsqrt(mean(g^2)+eps)*w
// ---------------------------------------------------------------------------
__global__ __launch_bounds__(256)
void gated_rmsnorm_kernel(float* __restrict__ y,
                          const float* __restrict__ zxbcdt,
                          const float* __restrict__ norm_w)
{
    long r = blockIdx.x;
    int tid = threadIdx.x;
    float* yr = y + r * DINNER;
    const float* zr = zxbcdt + r * DINPROJ;   // z = cols [0, DINNER)

    float vals[8];
    float ss = 0.f;
    #pragma unroll
    for (int i = 0; i < 8; i++) {
        int c = tid + i * 256;
        float z  = zr[c];
        float gv = yr[c] * (z / (1.f + expf(-z)));
        vals[i] = gv;
        ss = fmaf(gv, gv, ss);
    }

    __shared__ float sred[256];
    sred[tid] = ss;
    __syncthreads();
    #pragma unroll
    for (int off = 128; off > 0; off >>= 1) {
        if (tid < off) sred[tid] += sred[tid + off];
        __syncthreads();
    }
    float scale = rsqrtf(sred[0] / (float)DINNER + 1e-5f);

    #pragma unroll
    for (int i = 0; i < 8; i++) {
        int c = tid + i * 256;
        yr[c] = vals[i] * scale * norm_w[c];
    }
}

// ---------------------------------------------------------------------------
// Launch.  Inputs (metadata order): x, in_proj_w, conv_w, conv_b, norm_w,
//                                   out_proj_w, dt_bias, A_log, D
// ---------------------------------------------------------------------------
extern "C" void kernel_launch(void* const* d_in, const int* in_sizes, int n_in,
                              void* d_out, int out_size)
{
    const float* x          = (const float*)d_in[0];
    const float* in_proj_w  = (const float*)d_in[1];
    const float* conv_w     = (const float*)d_in[2];
    const float* conv_b     = (const float*)d_in[3];
    const float* norm_w     = (const float*)d_in[4];
    const float* out_proj_w = (const float*)d_in[5];
    const float* dt_bias    = (const float*)d_in[6];
    const float* A_log      = (const float*)d_in[7];
    const float* Dparam     = (const float*)d_in[8];
    float* out = (float*)d_out;

    float *zxbcdt, *convbuf, *ybuf;
    cudaGetSymbolAddress((void**)&zxbcdt,  g_zxbcdt);
    cudaGetSymbolAddress((void**)&convbuf, g_conv);
    cudaGetSymbolAddress((void**)&ybuf,    g_y);

    // 1) in_proj: [8192,1024] x [1024,4384]
    {
        dim3 grid((DINPROJ + 127) / 128, ROWS / 128);
        sgemm_kernel<<<grid, 256>>>(x, in_proj_w, zxbcdt, ROWS, DINPROJ, DMODEL);
    }

    // 2) conv + silu
    {
        long total = (long)ROWS * CONVDIM;
        int threads = 256;
        long blocks = (total + threads - 1) / threads;
        conv_silu_kernel<<<(unsigned)blocks, threads>>>(zxbcdt, conv_w, conv_b, convbuf);
    }

    // 3) selective scan (+ skip): 256 CTAs (b, h, p-quarter)
    scan_kernel<<<BATCH * NHEADS * 4, 128>>>(zxbcdt, convbuf, dt_bias, A_log,
                                             Dparam, ybuf);

    // 4) gated RMSNorm (in place on ybuf)
    gated_rmsnorm_kernel<<<ROWS, 256>>>(ybuf, zxbcdt, norm_w);

    // 5) out_proj: [8192,2048] x [2048,1024]
    {
        dim3 grid(DMODEL / 128, ROWS / 128);
        sgemm_kernel<<<grid, 256>>>(ybuf, out_proj_w, out, ROWS, DMODEL, DINNER);
    }
}

// round 4
// speedup vs baseline: 1.3358x; 1.3358x over previous
#include <cuda_runtime.h>
#include <cuda_bf16.h>
#include <math.h>
#include <stdint.h>

// ---------------------------------------------------------------------------
// Problem constants (Mamba2 block)
// ---------------------------------------------------------------------------
#define BATCH     2
#define SEQLEN    4096
#define DMODEL    1024
#define DSTATE    128
#define DCONV     4
#define HEADDIM   64
#define DINNER    2048
#define NHEADS    32
#define CONVDIM   2304              // DINNER + 2*DSTATE
#define DINPROJ   4384              // 2*DINNER + 2*DSTATE + NHEADS
#define ROWS      (BATCH*SEQLEN)    // 8192
#define DTCOL     (2*DINNER + 2*DSTATE)   // 4352

// Scratch (allocation-free rule: __device__ globals)
__device__ float g_zxbcdt[(size_t)ROWS * DINPROJ];
__device__ float g_conv  [(size_t)ROWS * CONVDIM];
__device__ float g_y     [(size_t)ROWS * DINNER];

__device__ __forceinline__ uint32_t f2tf32(float f) {
    uint32_t r;
    asm("cvt.rna.tf32.f32 %0, %1;" : "=r"(r) : "f"(f));
    return r;
}

// ---------------------------------------------------------------------------
// TF32 mma.sync GEMM: C[M,N] = A[M,K] * B[K,N], row-major fp32 in/out.
// CTA tile 128x128, BK=32, 256 threads (8 warps, 2x4), warp tile 64x32.
// mma.sync.m16n8k8 tf32; M,K multiples of 128/32; N ragged (guarded).
//
// Smem: As[m][k] stride 36 (A-frag LDS conflict-free: bank = 4*g + t4),
//       Bs[n][k] stride 33 (transposed from gmem [k][n] during staging).
// ---------------------------------------------------------------------------
#define BK 32
#define ASTRIDE 36
#define BSTRIDE 33

__global__ __launch_bounds__(256, 2)
void tf32_gemm_kernel(const float* __restrict__ A, const float* __restrict__ B,
                      float* __restrict__ C, int M, int N, int K)
{
    __shared__ uint32_t As[128 * ASTRIDE];   // 18432 B
    __shared__ uint32_t Bs[128 * BSTRIDE];   // 16896 B

    const int tid   = threadIdx.x;
    const int warp  = tid >> 5;
    const int lane  = tid & 31;
    const int g     = lane >> 2;       // group 0..7
    const int t4    = lane & 3;        // 0..3
    const int warpM = warp >> 2;       // 0..1
    const int warpN = warp & 3;        // 0..3
    const int rowC  = blockIdx.y * 128;
    const int colC  = blockIdx.x * 128;

    float acc[4][4][4];
    #pragma unroll
    for (int mi = 0; mi < 4; mi++)
        #pragma unroll
        for (int ni = 0; ni < 4; ni++)
            #pragma unroll
            for (int r = 0; r < 4; r++) acc[mi][ni][r] = 0.f;

    const int NC = K / BK;
    for (int ch = 0; ch < NC; ch++) {
        const int k0 = ch * BK;

        // ---- stage A: 128 x 32 = 1024 float4, 4 passes, conflict-free STS
        #pragma unroll
        for (int p = 0; p < 4; p++) {
            int i  = p * 256 + tid;
            int m  = i >> 3;          // 0..127
            int kq = i & 7;           // float4 index
            const float4 v = *(const float4*)(A + (size_t)(rowC + m) * K + k0 + kq * 4);
            uint32_t* dst = &As[m * ASTRIDE + kq * 4];
            dst[0] = f2tf32(v.x); dst[1] = f2tf32(v.y);
            dst[2] = f2tf32(v.z); dst[3] = f2tf32(v.w);
        }
        // ---- stage B with transpose: read [k][n] coalesced, write [n][k]
        #pragma unroll
        for (int p = 0; p < 4; p++) {
            int i  = p * 256 + tid;
            int kl = i >> 5;          // 0..31
            int nq = i & 31;          // float4 over n
            int gcol = colC + nq * 4;
            float4 v = make_float4(0.f, 0.f, 0.f, 0.f);
            if (gcol < N)             // N % 4 == 0 -> full float4 in-bounds
                v = *(const float4*)(B + (size_t)(k0 + kl) * N + gcol);
            Bs[(nq * 4 + 0) * BSTRIDE + kl] = f2tf32(v.x);
            Bs[(nq * 4 + 1) * BSTRIDE + kl] = f2tf32(v.y);
            Bs[(nq * 4 + 2) * BSTRIDE + kl] = f2tf32(v.z);
            Bs[(nq * 4 + 3) * BSTRIDE + kl] = f2tf32(v.w);
        }
        __syncthreads();

        // ---- compute: 4 k-steps of 8
        #pragma unroll
        for (int ks = 0; ks < 4; ks++) {
            const int kk = ks * 8;
            uint32_t af[4][4];
            #pragma unroll
            for (int mi = 0; mi < 4; mi++) {
                int m = warpM * 64 + mi * 16;
                af[mi][0] = As[(m + g)     * ASTRIDE + kk + t4];
                af[mi][1] = As[(m + g + 8) * ASTRIDE + kk + t4];
                af[mi][2] = As[(m + g)     * ASTRIDE + kk + t4 + 4];
                af[mi][3] = As[(m + g + 8) * ASTRIDE + kk + t4 + 4];
            }
            uint32_t bf[4][2];
            #pragma unroll
            for (int ni = 0; ni < 4; ni++) {
                int n = warpN * 32 + ni * 8;
                bf[ni][0] = Bs[(n + g) * BSTRIDE + kk + t4];
                bf[ni][1] = Bs[(n + g) * BSTRIDE + kk + t4 + 4];
            }
            #pragma unroll
            for (int mi = 0; mi < 4; mi++)
                #pragma unroll
                for (int ni = 0; ni < 4; ni++) {
                    asm volatile(
                        "mma.sync.aligned.m16n8k8.row.col.f32.tf32.tf32.f32 "
                        "{%0,%1,%2,%3}, {%4,%5,%6,%7}, {%8,%9}, {%0,%1,%2,%3};"
                        : "+f"(acc[mi][ni][0]), "+f"(acc[mi][ni][1]),
                          "+f"(acc[mi][ni][2]), "+f"(acc[mi][ni][3])
                        : "r"(af[mi][0]), "r"(af[mi][1]),
                          "r"(af[mi][2]), "r"(af[mi][3]),
                          "r"(bf[ni][0]), "r"(bf[ni][1]));
                }
        }
        __syncthreads();
    }

    // ---- epilogue: direct float2 stores (cols tig*2, tig*2+1 contiguous)
    #pragma unroll
    for (int mi = 0; mi < 4; mi++) {
        int r0 = rowC + warpM * 64 + mi * 16 + g;
        #pragma unroll
        for (int ni = 0; ni < 4; ni++) {
            int cc = colC + warpN * 32 + ni * 8 + t4 * 2;
            if (cc < N) {
                *(float2*)(C + (size_t)r0 * N + cc)       =
                    make_float2(acc[mi][ni][0], acc[mi][ni][1]);
                *(float2*)(C + (size_t)(r0 + 8) * N + cc) =
                    make_float2(acc[mi][ni][2], acc[mi][ni][3]);
            }
        }
    }
}

// ---------------------------------------------------------------------------
// Causal depthwise conv1d (K=4) + SiLU
// ---------------------------------------------------------------------------
__global__ void conv_silu_kernel(const float* __restrict__ zxbcdt,
                                 const float* __restrict__ conv_w,
                                 const float* __restrict__ conv_b,
                                 float* __restrict__ out)
{
    long idx = (long)blockIdx.x * blockDim.x + threadIdx.x;
    const long total = (long)ROWS * CONVDIM;
    if (idx >= total) return;
    int  c = (int)(idx % CONVDIM);
    long r = idx / CONVDIM;
    int  l = (int)(r & (SEQLEN - 1));

    const float* xcol = zxbcdt + r * DINPROJ + DINNER + c;
    float acc = conv_b[c];
    #pragma unroll
    for (int j = 0; j < DCONV; j++) {
        if (l - j >= 0)
            acc = fmaf(conv_w[j * CONVDIM + c], xcol[-(long)j * DINPROJ], acc);
    }
    out[idx] = acc / (1.f + expf(-acc));
}

// ---------------------------------------------------------------------------
// Selective scan, p-split: 256 CTAs of 128 threads, double-buffered staging,
// one __syncthreads per step. Skip connection folded in.
// ---------------------------------------------------------------------------
__global__ __launch_bounds__(128, 2)
void scan_kernel(const float* __restrict__ zxbcdt,
                 const float* __restrict__ convout,
                 const float* __restrict__ dt_bias,
                 const float* __restrict__ A_log,
                 const float* __restrict__ Dparam,
                 float* __restrict__ y)
{
    int bx  = blockIdx.x;
    int pq  = bx & 3;
    int h   = (bx >> 2) & 31;
    int b   = bx >> 7;
    int tid = threadIdx.x;
    int pl  = tid & 15;
    int nseg = tid >> 4;
    int n0  = nseg * 16;

    const float A   = -expf(A_log[h]);
    const float dtb = dt_bias[h];
    const float Dh  = Dparam[h];
    const int   pcol = h * HEADDIM + pq * 16;

    float s[16];
    #pragma unroll
    for (int j = 0; j < 16; j++) s[j] = 0.f;

    __shared__ float sx [2][16];
    __shared__ float sB [2][DSTATE];
    __shared__ float sC [2][DSTATE];
    __shared__ float sdt[2];
    __shared__ float sdec[2];
    __shared__ float red[2][128];

    const long rowbase = (long)b * SEQLEN;

    {
        const float* crow = convout + rowbase * CONVDIM;
        if (tid < 16) sx[0][tid] = crow[pcol + tid];
        sB[0][tid] = crow[DINNER + tid];
        sC[0][tid] = crow[DINNER + DSTATE + tid];
        if (tid == 0) {
            float v  = zxbcdt[rowbase * DINPROJ + DTCOL + h] + dtb;
            float dt = (v > 20.f) ? v : log1pf(expf(v));
            sdt[0]  = dt;
            sdec[0] = expf(A * dt);
        }
    }
    __syncthreads();

    for (int t = 0; t < SEQLEN; t++) {
        int q = t & 1;
        if (t + 1 < SEQLEN) {
            const float* crow = convout + (rowbase + t + 1) * CONVDIM;
            if (tid < 16) sx[q ^ 1][tid] = crow[pcol + tid];
            sB[q ^ 1][tid] = crow[DINNER + tid];
            sC[q ^ 1][tid] = crow[DINNER + DSTATE + tid];
            if (tid == 0) {
                float v  = zxbcdt[(rowbase + t + 1) * DINPROJ + DTCOL + h] + dtb;
                float dt = (v > 20.f) ? v : log1pf(expf(v));
                sdt[q ^ 1]  = dt;
                sdec[q ^ 1] = expf(A * dt);
            }
        }

        float dt  = sdt[q];
        float dec = sdec[q];
        float xv  = sx[q][pl];
        float xdt = xv * dt;
        float acc = 0.f;
        #pragma unroll
        for (int j = 0; j < 16; j++) {
            float sv = fmaf(s[j], dec, xdt * sB[q][n0 + j]);
            s[j] = sv;
            acc = fmaf(sv, sC[q][n0 + j], acc);
        }
        red[q][tid] = acc;
        __syncthreads();

        if (nseg == 0) {
            float yv = xv * Dh;
            #pragma unroll
            for (int k = 0; k < 8; k++) yv += red[q][k * 16 + pl];
            y[(rowbase + t) * DINNER + pcol + pl] = yv;
        }
    }
}

// ---------------------------------------------------------------------------
// Gated RMSNorm in place on y
// ---------------------------------------------------------------------------
__global__ __launch_bounds__(256)
void gated_rmsnorm_kernel(float* __restrict__ y,
                          const float* __restrict__ zxbcdt,
                          const float* __restrict__ norm_w)
{
    long r = blockIdx.x;
    int tid = threadIdx.x;
    float* yr = y + r * DINNER;
    const float* zr = zxbcdt + r * DINPROJ;

    float vals[8];
    float ss = 0.f;
    #pragma unroll
    for (int i = 0; i < 8; i++) {
        int c = tid + i * 256;
        float z  = zr[c];
        float gv = yr[c] * (z / (1.f + expf(-z)));
        vals[i] = gv;
        ss = fmaf(gv, gv, ss);
    }

    __shared__ float sred[256];
    sred[tid] = ss;
    __syncthreads();
    #pragma unroll
    for (int off = 128; off > 0; off >>= 1) {
        if (tid < off) sred[tid] += sred[tid + off];
        __syncthreads();
    }
    float scale = rsqrtf(sred[0] / (float)DINNER + 1e-5f);

    #pragma unroll
    for (int i = 0; i < 8; i++) {
        int c = tid + i * 256;
        yr[c] = vals[i] * scale * norm_w[c];
    }
}

// ---------------------------------------------------------------------------
// Launch. Inputs: x, in_proj_w, conv_w, conv_b, norm_w, out_proj_w,
//                 dt_bias, A_log, D
// ---------------------------------------------------------------------------
extern "C" void kernel_launch(void* const* d_in, const int* in_sizes, int n_in,
                              void* d_out, int out_size)
{
    const float* x          = (const float*)d_in[0];
    const float* in_proj_w  = (const float*)d_in[1];
    const float* conv_w     = (const float*)d_in[2];
    const float* conv_b     = (const float*)d_in[3];
    const float* norm_w     = (const float*)d_in[4];
    const float* out_proj_w = (const float*)d_in[5];
    const float* dt_bias    = (const float*)d_in[6];
    const float* A_log      = (const float*)d_in[7];
    const float* Dparam     = (const float*)d_in[8];
    float* out = (float*)d_out;

    float *zxbcdt, *convbuf, *ybuf;
    cudaGetSymbolAddress((void**)&zxbcdt,  g_zxbcdt);
    cudaGetSymbolAddress((void**)&convbuf, g_conv);
    cudaGetSymbolAddress((void**)&ybuf,    g_y);

    // 1) in_proj: [8192,1024] x [1024,4384]
    {
        dim3 grid((DINPROJ + 127) / 128, ROWS / 128);   // 35 x 64
        tf32_gemm_kernel<<<grid, 256>>>(x, in_proj_w, zxbcdt, ROWS, DINPROJ, DMODEL);
    }

    // 2) conv + silu
    {
        long total = (long)ROWS * CONVDIM;
        int threads = 256;
        long blocks = (total + threads - 1) / threads;
        conv_silu_kernel<<<(unsigned)blocks, threads>>>(zxbcdt, conv_w, conv_b, convbuf);
    }

    // 3) selective scan (+ skip)
    scan_kernel<<<BATCH * NHEADS * 4, 128>>>(zxbcdt, convbuf, dt_bias, A_log,
                                             Dparam, ybuf);

    // 4) gated RMSNorm
    gated_rmsnorm_kernel<<<ROWS, 256>>>(ybuf, zxbcdt, norm_w);

    // 5) out_proj: [8192,2048] x [2048,1024]
    {
        dim3 grid(DMODEL / 128, ROWS / 128);            // 8 x 64
        tf32_gemm_kernel<<<grid, 256>>>(ybuf, out_proj_w, out, ROWS, DMODEL, DINNER);
    }
}

// round 5
// speedup vs baseline: 3.0789x; 2.3048x over previous
#include <cuda_runtime.h>
#include <cuda_bf16.h>
#include <math.h>
#include <stdint.h>

// ---------------------------------------------------------------------------
// Problem constants (Mamba2 block)
// ---------------------------------------------------------------------------
#define BATCH     2
#define SEQLEN    4096
#define DMODEL    1024
#define DSTATE    128
#define DCONV     4
#define HEADDIM   64
#define DINNER    2048
#define NHEADS    32
#define CONVDIM   2304              // DINNER + 2*DSTATE
#define DINPROJ   4384              // 2*DINNER + 2*DSTATE + NHEADS
#define ROWS      (BATCH*SEQLEN)    // 8192
#define DTCOL     (2*DINNER + 2*DSTATE)   // 4352

// Scratch (allocation-free rule: __device__ globals)
__device__ float g_zxbcdt[(size_t)ROWS * DINPROJ];
__device__ float g_conv  [(size_t)ROWS * CONVDIM];
__device__ float g_y     [(size_t)ROWS * DINNER];
__device__ float g_xtf   [(size_t)ROWS * DMODEL];      // tf32-rounded x
__device__ float g_w1tf  [(size_t)DMODEL * DINPROJ];   // tf32-rounded in_proj_w
__device__ float g_w2tf  [(size_t)DINNER * DMODEL];    // tf32-rounded out_proj_w
__device__ float g_dt    [(size_t)ROWS * NHEADS];      // softplus(dt+bias)
__device__ float g_dec   [(size_t)ROWS * NHEADS];      // exp(A*dt)

__device__ __forceinline__ uint32_t f2tf32(float f) {
    uint32_t r;
    asm("cvt.rna.tf32.f32 %0, %1;" : "=r"(r) : "f"(f));
    return r;
}
__device__ __forceinline__ uint32_t smem_addr(const void* p) {
    return (uint32_t)__cvta_generic_to_shared(p);
}
__device__ __forceinline__ void cp16(uint32_t dst, const void* src, int sz) {
    asm volatile("cp.async.cg.shared.global [%0], [%1], 16, %2;"
                 :: "r"(dst), "l"(src), "r"(sz) : "memory");
}
__device__ __forceinline__ void cp4(uint32_t dst, const void* src) {
    asm volatile("cp.async.ca.shared.global [%0], [%1], 4;"
                 :: "r"(dst), "l"(src) : "memory");
}
#define CP_COMMIT() asm volatile("cp.async.commit_group;" ::: "memory")
#define CP_WAIT(n)  asm volatile("cp.async.wait_group %0;" :: "n"(n) : "memory")

// ---------------------------------------------------------------------------
// Elementwise tf32 rounding pre-pass (float4 vectorized; n % 4 == 0)
// ---------------------------------------------------------------------------
__global__ void cvt_tf32_kernel(const float* __restrict__ in,
                                float* __restrict__ out, long n4)
{
    long i = (long)blockIdx.x * blockDim.x + threadIdx.x;
    if (i >= n4) return;
    float4 v = ((const float4*)in)[i];
    float4 o;
    o.x = __uint_as_float(f2tf32(v.x));
    o.y = __uint_as_float(f2tf32(v.y));
    o.z = __uint_as_float(f2tf32(v.z));
    o.w = __uint_as_float(f2tf32(v.w));
    ((float4*)out)[i] = o;
}

// ---------------------------------------------------------------------------
// TF32 mma.sync GEMM with 3-stage cp.async pipeline.
// C[M,N] = A[M,K] * B[K,N]; A,B already tf32-rounded fp32; C fp32.
// CTA 128x128, BK=32, 256 threads (8 warps 2x4), warp 64x32.
// Smem/stage: As[128][36] (A-frag LDS bank 4g+t4 bijective -> conflict-free)
//             Bs[32][136] (untransposed; STS conflict-free; bf bank 8t4+g
//             bijective -> conflict-free)
// ---------------------------------------------------------------------------
#define GSTAGES 3
#define ASTR 36
#define BSTR 136
#define STAGE_WORDS (128*ASTR + 32*BSTR)            // 8960 words
#define GEMM_SMEM   (GSTAGES * STAGE_WORDS * 4)     // 107520 B

__global__ __launch_bounds__(256, 2)
void tf32_gemm_kernel(const float* __restrict__ A, const float* __restrict__ B,
                      float* __restrict__ C, int M, int N, int K)
{
    extern __shared__ uint32_t smem[];

    const int tid   = threadIdx.x;
    const int warp  = tid >> 5;
    const int lane  = tid & 31;
    const int g     = lane >> 2;
    const int t4    = lane & 3;
    const int warpM = warp >> 2;       // 0..1
    const int warpN = warp & 3;        // 0..3
    const int rowC  = blockIdx.y * 128;
    const int colC  = blockIdx.x * 128;
    const int NC    = K / 32;

    // staging: 8 cp.async(16B) per thread per stage
    auto stage_cp = [&](int chunk, int slot) {
        uint32_t* As = smem + slot * STAGE_WORDS;
        uint32_t* Bs = As + 128 * ASTR;
        const int k0 = chunk * 32;
        #pragma unroll
        for (int p = 0; p < 4; p++) {
            int i = p * 256 + tid;
            int m = i >> 3, kq = i & 7;
            cp16(smem_addr(As + m * ASTR + kq * 4),
                 A + (size_t)(rowC + m) * K + k0 + kq * 4, 16);
        }
        #pragma unroll
        for (int p = 0; p < 4; p++) {
            int i = p * 256 + tid;
            int kl = i >> 5, nq = i & 31;
            int gcol = colC + nq * 4;
            int ok = (gcol < N);
            cp16(smem_addr(Bs + kl * BSTR + nq * 4),
                 B + (size_t)(k0 + kl) * N + (ok ? gcol : 0), ok ? 16 : 0);
        }
    };

    float acc[4][4][4];
    #pragma unroll
    for (int mi = 0; mi < 4; mi++)
        #pragma unroll
        for (int ni = 0; ni < 4; ni++)
            #pragma unroll
            for (int r = 0; r < 4; r++) acc[mi][ni][r] = 0.f;

    stage_cp(0, 0); CP_COMMIT();
    stage_cp(1, 1); CP_COMMIT();

    for (int i = 0; i < NC; i++) {
        if (i < NC - 1) CP_WAIT(1); else CP_WAIT(0);
        __syncthreads();                     // stage i visible; compute(i-1) done
        if (i + 2 < NC) { stage_cp(i + 2, (i + 2) % GSTAGES); CP_COMMIT(); }

        const uint32_t* As = smem + (i % GSTAGES) * STAGE_WORDS;
        const uint32_t* Bs = As + 128 * ASTR;

        #pragma unroll
        for (int ks = 0; ks < 4; ks++) {
            const int kk = ks * 8;
            uint32_t af[4][4];
            #pragma unroll
            for (int mi = 0; mi < 4; mi++) {
                int m = warpM * 64 + mi * 16;
                af[mi][0] = As[(m + g)     * ASTR + kk + t4];
                af[mi][1] = As[(m + g + 8) * ASTR + kk + t4];
                af[mi][2] = As[(m + g)     * ASTR + kk + t4 + 4];
                af[mi][3] = As[(m + g + 8) * ASTR + kk + t4 + 4];
            }
            uint32_t bf[4][2];
            #pragma unroll
            for (int ni = 0; ni < 4; ni++) {
                int n = warpN * 32 + ni * 8 + g;
                bf[ni][0] = Bs[(kk + t4)     * BSTR + n];
                bf[ni][1] = Bs[(kk + t4 + 4) * BSTR + n];
            }
            #pragma unroll
            for (int mi = 0; mi < 4; mi++)
                #pragma unroll
                for (int ni = 0; ni < 4; ni++) {
                    asm volatile(
                        "mma.sync.aligned.m16n8k8.row.col.f32.tf32.tf32.f32 "
                        "{%0,%1,%2,%3}, {%4,%5,%6,%7}, {%8,%9}, {%0,%1,%2,%3};"
                        : "+f"(acc[mi][ni][0]), "+f"(acc[mi][ni][1]),
                          "+f"(acc[mi][ni][2]), "+f"(acc[mi][ni][3])
                        : "r"(af[mi][0]), "r"(af[mi][1]),
                          "r"(af[mi][2]), "r"(af[mi][3]),
                          "r"(bf[ni][0]), "r"(bf[ni][1]));
                }
        }
    }

    // epilogue: direct float2 stores
    #pragma unroll
    for (int mi = 0; mi < 4; mi++) {
        int r0 = rowC + warpM * 64 + mi * 16 + g;
        #pragma unroll
        for (int ni = 0; ni < 4; ni++) {
            int cc = colC + warpN * 32 + ni * 8 + t4 * 2;
            if (cc < N) {
                *(float2*)(C + (size_t)r0 * N + cc)       =
                    make_float2(acc[mi][ni][0], acc[mi][ni][1]);
                *(float2*)(C + (size_t)(r0 + 8) * N + cc) =
                    make_float2(acc[mi][ni][2], acc[mi][ni][3]);
            }
        }
    }
}

// ---------------------------------------------------------------------------
// Causal depthwise conv1d (K=4) + SiLU
// ---------------------------------------------------------------------------
__global__ void conv_silu_kernel(const float* __restrict__ zxbcdt,
                                 const float* __restrict__ conv_w,
                                 const float* __restrict__ conv_b,
                                 float* __restrict__ out)
{
    long idx = (long)blockIdx.x * blockDim.x + threadIdx.x;
    const long total = (long)ROWS * CONVDIM;
    if (idx >= total) return;
    int  c = (int)(idx % CONVDIM);
    long r = idx / CONVDIM;
    int  l = (int)(r & (SEQLEN - 1));

    const float* xcol = zxbcdt + r * DINPROJ + DINNER + c;
    float acc = conv_b[c];
    #pragma unroll
    for (int j = 0; j < DCONV; j++) {
        if (l - j >= 0)
            acc = fmaf(conv_w[j * CONVDIM + c], xcol[-(long)j * DINPROJ], acc);
    }
    out[idx] = acc / (1.f + expf(-acc));
}

// ---------------------------------------------------------------------------
// dt / decay precompute: dt = softplus(dt_raw + bias), dec = exp(A*dt)
// ---------------------------------------------------------------------------
__global__ void dtdec_kernel(const float* __restrict__ zxbcdt,
                             const float* __restrict__ dt_bias,
                             const float* __restrict__ A_log,
                             float* __restrict__ dt_out,
                             float* __restrict__ dec_out)
{
    long idx = (long)blockIdx.x * blockDim.x + threadIdx.x;
    if (idx >= (long)ROWS * NHEADS) return;
    int  h = (int)(idx & (NHEADS - 1));
    long r = idx >> 5;
    float v  = zxbcdt[r * DINPROJ + DTCOL + h] + dt_bias[h];
    float dt = (v > 20.f) ? v : log1pf(expf(v));
    dt_out[idx]  = dt;
    dec_out[idx] = expf(-expf(A_log[h]) * dt);
}

// ---------------------------------------------------------------------------
// Selective scan, p-split (256 CTAs of 128 threads), 4-stage cp.async ring.
// Stage layout (words): B[0..127], C[128..255], x[256..271], dt[272], dec[273].
// ---------------------------------------------------------------------------
#define SC_WORDS 276

__global__ __launch_bounds__(128)
void scan_kernel(const float* __restrict__ convout,
                 const float* __restrict__ dtbuf,
                 const float* __restrict__ decbuf,
                 const float* __restrict__ Dparam,
                 float* __restrict__ y)
{
    int bx  = blockIdx.x;
    int pq  = bx & 3;
    int h   = (bx >> 2) & 31;
    int b   = bx >> 7;
    int tid = threadIdx.x;
    int pl  = tid & 15;
    int nseg = tid >> 4;
    int n0  = nseg * 16;

    const float Dh   = Dparam[h];
    const int   pcol = h * HEADDIM + pq * 16;
    const long  rowbase = (long)b * SEQLEN;

    float s[16];
    #pragma unroll
    for (int j = 0; j < 16; j++) s[j] = 0.f;

    __shared__ float stg[4][SC_WORDS];
    __shared__ float red[128];

    auto issue = [&](int t, int slot) {
        const float* crow = convout + (rowbase + t) * CONVDIM;
        uint32_t base = smem_addr(&stg[slot][0]);
        cp4(base + (uint32_t)tid * 4,         crow + DINNER + tid);
        cp4(base + (uint32_t)(128 + tid) * 4, crow + DINNER + DSTATE + tid);
        if (tid < 16) cp4(base + (uint32_t)(256 + tid) * 4, crow + pcol + tid);
        if (tid == 16) cp4(base + 272 * 4, dtbuf  + (rowbase + t) * NHEADS + h);
        if (tid == 17) cp4(base + 273 * 4, decbuf + (rowbase + t) * NHEADS + h);
    };

    issue(0, 0); CP_COMMIT();
    issue(1, 1); CP_COMMIT();
    issue(2, 2); CP_COMMIT();

    for (int t = 0; t < SEQLEN; t++) {
        int slot = t & 3;
        if (t + 3 < SEQLEN) {
            issue(t + 3, (t + 3) & 3);   // slot (t-1)&3: consumed, barrier-cleared
            CP_COMMIT();
            CP_WAIT(3);
        } else {
            int rem = SEQLEN - 1 - t;    // 2, 1, 0
            if (rem == 2) CP_WAIT(2);
            else if (rem == 1) CP_WAIT(1);
            else CP_WAIT(0);
        }
        __syncthreads();                 // stage t visible to all threads

        const float* st = stg[slot];
        float dt  = st[272];
        float dec = st[273];
        float xv  = st[256 + pl];
        float xdt = xv * dt;
        float acc = 0.f;
        #pragma unroll
        for (int j = 0; j < 16; j++) {
            float sv = fmaf(s[j], dec, xdt * st[n0 + j]);
            s[j] = sv;
            acc = fmaf(sv, st[128 + n0 + j], acc);
        }
        red[tid] = acc;
        __syncthreads();

        if (nseg == 0) {
            float yv = xv * Dh;
            #pragma unroll
            for (int k = 0; k < 8; k++) yv += red[k * 16 + pl];
            y[(rowbase + t) * DINNER + pcol + pl] = yv;
        }
    }
}

// ---------------------------------------------------------------------------
// Gated RMSNorm in place on y; output tf32-rounded (feeds out_proj A).
// ---------------------------------------------------------------------------
__global__ __launch_bounds__(256)
void gated_rmsnorm_kernel(float* __restrict__ y,
                          const float* __restrict__ zxbcdt,
                          const float* __restrict__ norm_w)
{
    long r = blockIdx.x;
    int tid = threadIdx.x;
    float* yr = y + r * DINNER;
    const float* zr = zxbcdt + r * DINPROJ;

    float vals[8];
    float ss = 0.f;
    #pragma unroll
    for (int i = 0; i < 8; i++) {
        int c = tid + i * 256;
        float z  = zr[c];
        float gv = yr[c] * (z / (1.f + expf(-z)));
        vals[i] = gv;
        ss = fmaf(gv, gv, ss);
    }

    __shared__ float sred[256];
    sred[tid] = ss;
    __syncthreads();
    #pragma unroll
    for (int off = 128; off > 0; off >>= 1) {
        if (tid < off) sred[tid] += sred[tid + off];
        __syncthreads();
    }
    float scale = rsqrtf(sred[0] / (float)DINNER + 1e-5f);

    #pragma unroll
    for (int i = 0; i < 8; i++) {
        int c = tid + i * 256;
        yr[c] = __uint_as_float(f2tf32(vals[i] * scale * norm_w[c]));
    }
}

// ---------------------------------------------------------------------------
// Launch. Inputs: x, in_proj_w, conv_w, conv_b, norm_w, out_proj_w,
//                 dt_bias, A_log, D
// ---------------------------------------------------------------------------
extern "C" void kernel_launch(void* const* d_in, const int* in_sizes, int n_in,
                              void* d_out, int out_size)
{
    const float* x          = (const float*)d_in[0];
    const float* in_proj_w  = (const float*)d_in[1];
    const float* conv_w     = (const float*)d_in[2];
    const float* conv_b     = (const float*)d_in[3];
    const float* norm_w     = (const float*)d_in[4];
    const float* out_proj_w = (const float*)d_in[5];
    const float* dt_bias    = (const float*)d_in[6];
    const float* A_log      = (const float*)d_in[7];
    const float* Dparam     = (const float*)d_in[8];
    float* out = (float*)d_out;

    float *zxbcdt, *convbuf, *ybuf, *xtf, *w1tf, *w2tf, *dtb, *decb;
    cudaGetSymbolAddress((void**)&zxbcdt,  g_zxbcdt);
    cudaGetSymbolAddress((void**)&convbuf, g_conv);
    cudaGetSymbolAddress((void**)&ybuf,    g_y);
    cudaGetSymbolAddress((void**)&xtf,     g_xtf);
    cudaGetSymbolAddress((void**)&w1tf,    g_w1tf);
    cudaGetSymbolAddress((void**)&w2tf,    g_w2tf);
    cudaGetSymbolAddress((void**)&dtb,     g_dt);
    cudaGetSymbolAddress((void**)&decb,    g_dec);

    // Not a stream op: executes immediately even during graph capture.
    cudaFuncSetAttribute(tf32_gemm_kernel,
                         cudaFuncAttributeMaxDynamicSharedMemorySize, GEMM_SMEM);

    // 0) tf32 rounding pre-passes
    {
        long n4;
        n4 = (long)ROWS * DMODEL / 4;
        cvt_tf32_kernel<<<(unsigned)((n4 + 255) / 256), 256>>>(x, xtf, n4);
        n4 = (long)DMODEL * DINPROJ / 4;
        cvt_tf32_kernel<<<(unsigned)((n4 + 255) / 256), 256>>>(in_proj_w, w1tf, n4);
        n4 = (long)DINNER * DMODEL / 4;
        cvt_tf32_kernel<<<(unsigned)((n4 + 255) / 256), 256>>>(out_proj_w, w2tf, n4);
    }

    // 1) in_proj: [8192,1024] x [1024,4384]
    {
        dim3 grid((DINPROJ + 127) / 128, ROWS / 128);   // 35 x 64
        tf32_gemm_kernel<<<grid, 256, GEMM_SMEM>>>(xtf, w1tf, zxbcdt,
                                                   ROWS, DINPROJ, DMODEL);
    }

    // 2) conv + silu
    {
        long total = (long)ROWS * CONVDIM;
        conv_silu_kernel<<<(unsigned)((total + 255) / 256), 256>>>(
            zxbcdt, conv_w, conv_b, convbuf);
    }

    // 3) dt / decay precompute
    {
        long total = (long)ROWS * NHEADS;
        dtdec_kernel<<<(unsigned)((total + 255) / 256), 256>>>(
            zxbcdt, dt_bias, A_log, dtb, decb);
    }

    // 4) selective scan (+ skip)
    scan_kernel<<<BATCH * NHEADS * 4, 128>>>(convbuf, dtb, decb, Dparam, ybuf);

    // 5) gated RMSNorm (output tf32-rounded)
    gated_rmsnorm_kernel<<<ROWS, 256>>>(ybuf, zxbcdt, norm_w);

    // 6) out_proj: [8192,2048] x [2048,1024]
    {
        dim3 grid(DMODEL / 128, ROWS / 128);            // 8 x 64
        tf32_gemm_kernel<<<grid, 256, GEMM_SMEM>>>(ybuf, w2tf, out,
                                                   ROWS, DMODEL, DINNER);
    }
}

// round 7
// speedup vs baseline: 5.3528x; 1.7386x over previous
#include <cuda_runtime.h>
#include <cuda_bf16.h>
#include <math.h>
#include <stdint.h>

// ---------------------------------------------------------------------------
// Problem constants (Mamba2 block)
// ---------------------------------------------------------------------------
#define BATCH     2
#define SEQLEN    4096
#define DMODEL    1024
#define DSTATE    128
#define DCONV     4
#define HEADDIM   64
#define DINNER    2048
#define NHEADS    32
#define CONVDIM   2304              // DINNER + 2*DSTATE
#define DINPROJ   4384              // 2*DINNER + 2*DSTATE + NHEADS
#define ROWS      (BATCH*SEQLEN)    // 8192
#define DTCOL     (2*DINNER + 2*DSTATE)   // 4352

#define T_CH      64                // chunk length
#define NCHUNK    (SEQLEN / T_CH)   // 64 chunks per (b,h)
#define NCTA_CH   (BATCH * NHEADS * NCHUNK)   // 4096

// Scratch (allocation-free rule: __device__ globals)
__device__ float g_zxbcdt[(size_t)ROWS * DINPROJ];
__device__ float g_conv  [(size_t)ROWS * CONVDIM];
__device__ float g_y     [(size_t)ROWS * DINNER];
__device__ float g_xtf   [(size_t)ROWS * DMODEL];
__device__ float g_w1tf  [(size_t)DMODEL * DINPROJ];
__device__ float g_w2tf  [(size_t)DINNER * DMODEL];
__device__ float g_dt    [(size_t)ROWS * NHEADS];
__device__ float g_sinc  [(size_t)NCTA_CH * HEADDIM * DSTATE];  // chunk state increments
__device__ float g_state0[(size_t)NCTA_CH * HEADDIM * DSTATE];  // chunk start states
__device__ float g_et    [(size_t)NCTA_CH * T_CH];              // exp(A*S_t)
__device__ float g_cdec  [(size_t)NCTA_CH];                     // exp(A*S_T)

__device__ __forceinline__ uint32_t f2tf32(float f) {
    uint32_t r;
    asm("cvt.rna.tf32.f32 %0, %1;" : "=r"(r) : "f"(f));
    return r;
}
__device__ __forceinline__ float tfr(float f) {
    return __uint_as_float(f2tf32(f));
}
__device__ __forceinline__ uint32_t smem_addr(const void* p) {
    return (uint32_t)__cvta_generic_to_shared(p);
}
__device__ __forceinline__ void cp16(uint32_t dst, const void* src, int sz) {
    asm volatile("cp.async.cg.shared.global [%0], [%1], 16, %2;"
                 :: "r"(dst), "l"(src), "r"(sz) : "memory");
}
#define CP_COMMIT() asm volatile("cp.async.commit_group;" ::: "memory")
#define CP_WAIT(n)  asm volatile("cp.async.wait_group %0;" :: "n"(n) : "memory")

#define MMA_TF32(acc, a0, a1, a2, a3, b0, b1)                               \
    asm volatile(                                                           \
        "mma.sync.aligned.m16n8k8.row.col.f32.tf32.tf32.f32 "               \
        "{%0,%1,%2,%3}, {%4,%5,%6,%7}, {%8,%9}, {%0,%1,%2,%3};"             \
        : "+f"((acc)[0]), "+f"((acc)[1]), "+f"((acc)[2]), "+f"((acc)[3])    \
        : "r"(a0), "r"(a1), "r"(a2), "r"(a3), "r"(b0), "r"(b1))

// ---------------------------------------------------------------------------
// Elementwise tf32 rounding pre-pass
// ---------------------------------------------------------------------------
__global__ void cvt_tf32_kernel(const float* __restrict__ in,
                                float* __restrict__ out, long n4)
{
    long i = (long)blockIdx.x * blockDim.x + threadIdx.x;
    if (i >= n4) return;
    float4 v = ((const float4*)in)[i];
    float4 o = make_float4(tfr(v.x), tfr(v.y), tfr(v.z), tfr(v.w));
    ((float4*)out)[i] = o;
}

// ---------------------------------------------------------------------------
// TF32 mma.sync GEMM with 3-stage cp.async pipeline.
// ---------------------------------------------------------------------------
#define GSTAGES 3
#define ASTR 36
#define BSTR 136
#define STAGE_WORDS (128*ASTR + 32*BSTR)
#define GEMM_SMEM   (GSTAGES * STAGE_WORDS * 4)

__global__ __launch_bounds__(256, 2)
void tf32_gemm_kernel(const float* __restrict__ A, const float* __restrict__ B,
                      float* __restrict__ C, int M, int N, int K)
{
    extern __shared__ uint32_t smem[];

    const int tid   = threadIdx.x;
    const int warp  = tid >> 5;
    const int lane  = tid & 31;
    const int g     = lane >> 2;
    const int t4    = lane & 3;
    const int warpM = warp >> 2;
    const int warpN = warp & 3;
    const int rowC  = blockIdx.y * 128;
    const int colC  = blockIdx.x * 128;
    const int NC    = K / 32;

    auto stage_cp = [&](int chunk, int slot) {
        uint32_t* As = smem + slot * STAGE_WORDS;
        uint32_t* Bs = As + 128 * ASTR;
        const int k0 = chunk * 32;
        #pragma unroll
        for (int p = 0; p < 4; p++) {
            int i = p * 256 + tid;
            int m = i >> 3, kq = i & 7;
            cp16(smem_addr(As + m * ASTR + kq * 4),
                 A + (size_t)(rowC + m) * K + k0 + kq * 4, 16);
        }
        #pragma unroll
        for (int p = 0; p < 4; p++) {
            int i = p * 256 + tid;
            int kl = i >> 5, nq = i & 31;
            int gcol = colC + nq * 4;
            int ok = (gcol < N);
            cp16(smem_addr(Bs + kl * BSTR + nq * 4),
                 B + (size_t)(k0 + kl) * N + (ok ? gcol : 0), ok ? 16 : 0);
        }
    };

    float acc[4][4][4];
    #pragma unroll
    for (int mi = 0; mi < 4; mi++)
        #pragma unroll
        for (int ni = 0; ni < 4; ni++)
            #pragma unroll
            for (int r = 0; r < 4; r++) acc[mi][ni][r] = 0.f;

    stage_cp(0, 0); CP_COMMIT();
    stage_cp(1, 1); CP_COMMIT();

    for (int i = 0; i < NC; i++) {
        if (i < NC - 1) CP_WAIT(1); else CP_WAIT(0);
        __syncthreads();
        if (i + 2 < NC) { stage_cp(i + 2, (i + 2) % GSTAGES); CP_COMMIT(); }

        const uint32_t* As = smem + (i % GSTAGES) * STAGE_WORDS;
        const uint32_t* Bs = As + 128 * ASTR;

        #pragma unroll
        for (int ks = 0; ks < 4; ks++) {
            const int kk = ks * 8;
            uint32_t af[4][4];
            #pragma unroll
            for (int mi = 0; mi < 4; mi++) {
                int m = warpM * 64 + mi * 16;
                af[mi][0] = As[(m + g)     * ASTR + kk + t4];
                af[mi][1] = As[(m + g + 8) * ASTR + kk + t4];
                af[mi][2] = As[(m + g)     * ASTR + kk + t4 + 4];
                af[mi][3] = As[(m + g + 8) * ASTR + kk + t4 + 4];
            }
            uint32_t bf[4][2];
            #pragma unroll
            for (int ni = 0; ni < 4; ni++) {
                int n = warpN * 32 + ni * 8 + g;
                bf[ni][0] = Bs[(kk + t4)     * BSTR + n];
                bf[ni][1] = Bs[(kk + t4 + 4) * BSTR + n];
            }
            #pragma unroll
            for (int mi = 0; mi < 4; mi++)
                #pragma unroll
                for (int ni = 0; ni < 4; ni++)
                    MMA_TF32(acc[mi][ni], af[mi][0], af[mi][1], af[mi][2],
                             af[mi][3], bf[ni][0], bf[ni][1]);
        }
    }

    #pragma unroll
    for (int mi = 0; mi < 4; mi++) {
        int r0 = rowC + warpM * 64 + mi * 16 + g;
        #pragma unroll
        for (int ni = 0; ni < 4; ni++) {
            int cc = colC + warpN * 32 + ni * 8 + t4 * 2;
            if (cc < N) {
                *(float2*)(C + (size_t)r0 * N + cc)       =
                    make_float2(acc[mi][ni][0], acc[mi][ni][1]);
                *(float2*)(C + (size_t)(r0 + 8) * N + cc) =
                    make_float2(acc[mi][ni][2], acc[mi][ni][3]);
            }
        }
    }
}

// ---------------------------------------------------------------------------
// Causal depthwise conv1d (K=4) + SiLU
// ---------------------------------------------------------------------------
__global__ void conv_silu_kernel(const float* __restrict__ zxbcdt,
                                 const float* __restrict__ conv_w,
                                 const float* __restrict__ conv_b,
                                 float* __restrict__ out)
{
    long idx = (long)blockIdx.x * blockDim.x + threadIdx.x;
    const long total = (long)ROWS * CONVDIM;
    if (idx >= total) return;
    int  c = (int)(idx % CONVDIM);
    long r = idx / CONVDIM;
    int  l = (int)(r & (SEQLEN - 1));

    const float* xcol = zxbcdt + r * DINPROJ + DINNER + c;
    float acc = conv_b[c];
    #pragma unroll
    for (int j = 0; j < DCONV; j++) {
        if (l - j >= 0)
            acc = fmaf(conv_w[j * CONVDIM + c], xcol[-(long)j * DINPROJ], acc);
    }
    out[idx] = acc / (1.f + expf(-acc));
}

// ---------------------------------------------------------------------------
// dt precompute: dt = softplus(dt_raw + bias)
// ---------------------------------------------------------------------------
__global__ void dt_kernel(const float* __restrict__ zxbcdt,
                          const float* __restrict__ dt_bias,
                          float* __restrict__ dt_out)
{
    long idx = (long)blockIdx.x * blockDim.x + threadIdx.x;
    if (idx >= (long)ROWS * NHEADS) return;
    int  h = (int)(idx & (NHEADS - 1));
    long r = idx >> 5;
    float v  = zxbcdt[r * DINPROJ + DTCOL + h] + dt_bias[h];
    dt_out[idx] = (v > 20.f) ? v : log1pf(expf(v));
}

// ---------------------------------------------------------------------------
// Chunked scan, intra-chunk kernel. One CTA per (b, h, chunk of 64).
// Y_intra[t][p] = sum_{s<=t} e^{A(S_t-S_s)} dt_s (C_t.B_s) x_s[p] + D_h x_t[p]
// SI[p][n] = sum_t dt_t e^{A(S_T-S_t)} x_t[p] B_t[n]
// ---------------------------------------------------------------------------
#define CH_SMEM ((64*132 + 64*132 + 64*68 + 64*68 + 4*64) * 4)

__global__ __launch_bounds__(256, 2)
void chunk_kernel(const float* __restrict__ convout,
                  const float* __restrict__ dtbuf,
                  const float* __restrict__ A_log,
                  const float* __restrict__ Dparam,
                  float* __restrict__ y,
                  float* __restrict__ sinc,
                  float* __restrict__ etbuf,
                  float* __restrict__ cdec)
{
    extern __shared__ float sm[];
    float* Bs  = sm;                  // [64][132]  B[t][n]
    float* Cs  = Bs + 64 * 132;       // [64][132]  C[t][n]; reused as Ms[64][68]
    float* Xs  = Cs + 64 * 132;       // [64][68]   x[t][p]
    float* Xw  = Xs + 64 * 68;        // [64][68]   weighted x^T [p][t]
    float* sS  = Xw + 64 * 68;        // 64  inclusive cumsum of dt
    float* sdt = sS + 64;             // 64
    float* swS = sdt + 64;            // 64  dt_t * e^{A(S_T - S_t)}
    float* Ms  = Cs;                  // [64][68]   masked/weighted gram

    const int ci    = blockIdx.x;
    const int chunk = ci & (NCHUNK - 1);
    const int h     = (ci >> 6) & (NHEADS - 1);
    const int b     = ci >> 11;
    const long r0   = (long)b * SEQLEN + chunk * T_CH;
    const int tid   = threadIdx.x;
    const int warp  = tid >> 5;
    const int lane  = tid & 31;
    const int g     = lane >> 2;
    const int t4    = lane & 3;
    const int wM    = warp >> 2;      // 0..1
    const int wN    = warp & 3;       // 0..3

    const float A  = -expf(A_log[h]);
    const float Dh = Dparam[h];

    // ---- stage B, C, X tiles (tf32-rounded)
    #pragma unroll
    for (int j = 0; j < 8; j++) {
        int idx = j * 256 + tid;
        int t = idx >> 5, q = idx & 31;
        const float* row = convout + (r0 + t) * CONVDIM;
        float4 vb = *(const float4*)(row + DINNER + q * 4);
        float* db = &Bs[t * 132 + q * 4];
        db[0] = tfr(vb.x); db[1] = tfr(vb.y); db[2] = tfr(vb.z); db[3] = tfr(vb.w);
        float4 vc = *(const float4*)(row + DINNER + DSTATE + q * 4);
        float* dc = &Cs[t * 132 + q * 4];
        dc[0] = tfr(vc.x); dc[1] = tfr(vc.y); dc[2] = tfr(vc.z); dc[3] = tfr(vc.w);
    }
    #pragma unroll
    for (int j = 0; j < 4; j++) {
        int idx = j * 256 + tid;
        int t = idx >> 4, q = idx & 15;
        float4 v = *(const float4*)(convout + (r0 + t) * CONVDIM + h * HEADDIM + q * 4);
        float* d = &Xs[t * 68 + q * 4];
        d[0] = tfr(v.x); d[1] = tfr(v.y); d[2] = tfr(v.z); d[3] = tfr(v.w);
    }
    if (tid < 64) {
        float d = dtbuf[(r0 + tid) * NHEADS + h];
        sdt[tid] = d;
        sS[tid]  = d;
    }
    __syncthreads();

    // ---- inclusive cumsum of dt (Hillis-Steele, 6 steps)
    #pragma unroll
    for (int off = 1; off < 64; off <<= 1) {
        float v = 0.f;
        if (tid < 64 && tid >= off) v = sS[tid - off];
        __syncthreads();
        if (tid < 64) sS[tid] += v;
        __syncthreads();
    }
    if (tid < 64) {
        float St = sS[tid], ST = sS[63];
        swS[tid] = sdt[tid] * __expf(A * (ST - St));
        etbuf[(size_t)ci * T_CH + tid] = __expf(A * St);
    }
    if (tid == 0) cdec[ci] = __expf(A * sS[63]);
    __syncthreads();

    // ---- Gram G[t][s] = sum_n C[t][n] B[s][n]
    float acc[2][2][4];
    #pragma unroll
    for (int mi = 0; mi < 2; mi++)
        #pragma unroll
        for (int ni = 0; ni < 2; ni++)
            #pragma unroll
            for (int r = 0; r < 4; r++) acc[mi][ni][r] = 0.f;

    #pragma unroll
    for (int ks = 0; ks < 16; ks++) {
        const int kk = ks * 8;
        uint32_t af[2][4], bf[2][2];
        #pragma unroll
        for (int mi = 0; mi < 2; mi++) {
            int m = wM * 32 + mi * 16;
            af[mi][0] = __float_as_uint(Cs[(m + g)     * 132 + kk + t4]);
            af[mi][1] = __float_as_uint(Cs[(m + g + 8) * 132 + kk + t4]);
            af[mi][2] = __float_as_uint(Cs[(m + g)     * 132 + kk + t4 + 4]);
            af[mi][3] = __float_as_uint(Cs[(m + g + 8) * 132 + kk + t4 + 4]);
        }
        #pragma unroll
        for (int ni = 0; ni < 2; ni++) {
            int s = wN * 16 + ni * 8 + g;
            bf[ni][0] = __float_as_uint(Bs[s * 132 + kk + t4]);
            bf[ni][1] = __float_as_uint(Bs[s * 132 + kk + t4 + 4]);
        }
        #pragma unroll
        for (int mi = 0; mi < 2; mi++)
            #pragma unroll
            for (int ni = 0; ni < 2; ni++)
                MMA_TF32(acc[mi][ni], af[mi][0], af[mi][1], af[mi][2],
                         af[mi][3], bf[ni][0], bf[ni][1]);
    }
    __syncthreads();   // Cs reads complete before Ms overwrite

    // ---- mask + decay-weight -> Ms[t][s]
    #pragma unroll
    for (int mi = 0; mi < 2; mi++) {
        #pragma unroll
        for (int ni = 0; ni < 2; ni++) {
            int tb = wM * 32 + mi * 16;
            int sb = wN * 16 + ni * 8 + 2 * t4;
            #pragma unroll
            for (int r = 0; r < 4; r++) {
                int tt = tb + g + ((r >= 2) ? 8 : 0);
                int ss = sb + (r & 1);
                float w = 0.f;
                if (ss <= tt) w = sdt[ss] * __expf(A * (sS[tt] - sS[ss]));
                Ms[tt * 68 + ss] = tfr(acc[mi][ni][r] * w);
            }
        }
    }
    // ---- build weighted transposed X: Xw[p][t] = wSI_t * x[t][p]
    #pragma unroll
    for (int j = 0; j < 16; j++) {
        int idx = j * 256 + tid;
        int p = idx >> 6, t = idx & 63;
        Xw[p * 68 + t] = tfr(swS[t] * Xs[t * 68 + p]);
    }
    __syncthreads();

    // ---- Y_intra = M . X : out [t=64][p=64], K=s=64
    float acc2[2][2][4];
    #pragma unroll
    for (int mi = 0; mi < 2; mi++)
        #pragma unroll
        for (int ni = 0; ni < 2; ni++)
            #pragma unroll
            for (int r = 0; r < 4; r++) acc2[mi][ni][r] = 0.f;

    #pragma unroll
    for (int ks = 0; ks < 8; ks++) {
        const int kk = ks * 8;
        uint32_t af[2][4], bf[2][2];
        #pragma unroll
        for (int mi = 0; mi < 2; mi++) {
            int m = wM * 32 + mi * 16;
            af[mi][0] = __float_as_uint(Ms[(m + g)     * 68 + kk + t4]);
            af[mi][1] = __float_as_uint(Ms[(m + g + 8) * 68 + kk + t4]);
            af[mi][2] = __float_as_uint(Ms[(m + g)     * 68 + kk + t4 + 4]);
            af[mi][3] = __float_as_uint(Ms[(m + g + 8) * 68 + kk + t4 + 4]);
        }
        #pragma unroll
        for (int ni = 0; ni < 2; ni++) {
            int p = wN * 16 + ni * 8 + g;
            bf[ni][0] = __float_as_uint(Xs[(kk + t4)     * 68 + p]);
            bf[ni][1] = __float_as_uint(Xs[(kk + t4 + 4) * 68 + p]);
        }
        #pragma unroll
        for (int mi = 0; mi < 2; mi++)
            #pragma unroll
            for (int ni = 0; ni < 2; ni++)
                MMA_TF32(acc2[mi][ni], af[mi][0], af[mi][1], af[mi][2],
                         af[mi][3], bf[ni][0], bf[ni][1]);
    }
    // epilogue: y = Y_intra + D*x
    #pragma unroll
    for (int mi = 0; mi < 2; mi++) {
        #pragma unroll
        for (int ni = 0; ni < 2; ni++) {
            int tb = wM * 32 + mi * 16;
            int pb = wN * 16 + ni * 8 + 2 * t4;
            int t0 = tb + g, t1 = tb + g + 8;
            float2 o0 = make_float2(
                acc2[mi][ni][0] + Dh * Xs[t0 * 68 + pb],
                acc2[mi][ni][1] + Dh * Xs[t0 * 68 + pb + 1]);
            float2 o1 = make_float2(
                acc2[mi][ni][2] + Dh * Xs[t1 * 68 + pb],
                acc2[mi][ni][3] + Dh * Xs[t1 * 68 + pb + 1]);
            *(float2*)(y + (r0 + t0) * DINNER + h * HEADDIM + pb) = o0;
            *(float2*)(y + (r0 + t1) * DINNER + h * HEADDIM + pb) = o1;
        }
    }

    // ---- SI[p][n] = sum_t Xw[p][t] B[t][n] : out [64][128], K=t=64
    float acc3[2][4][4];
    #pragma unroll
    for (int mi = 0; mi < 2; mi++)
        #pragma unroll
        for (int ni = 0; ni < 4; ni++)
            #pragma unroll
            for (int r = 0; r < 4; r++) acc3[mi][ni][r] = 0.f;

    #pragma unroll
    for (int ks = 0; ks < 8; ks++) {
        const int kk = ks * 8;
        uint32_t af[2][4], bf[4][2];
        #pragma unroll
        for (int mi = 0; mi < 2; mi++) {
            int p = wM * 32 + mi * 16;
            af[mi][0] = __float_as_uint(Xw[(p + g)     * 68 + kk + t4]);
            af[mi][1] = __float_as_uint(Xw[(p + g + 8) * 68 + kk + t4]);
            af[mi][2] = __float_as_uint(Xw[(p + g)     * 68 + kk + t4 + 4]);
            af[mi][3] = __float_as_uint(Xw[(p + g + 8) * 68 + kk + t4 + 4]);
        }
        #pragma unroll
        for (int ni = 0; ni < 4; ni++) {
            int n = wN * 32 + ni * 8 + g;
            bf[ni][0] = __float_as_uint(Bs[(kk + t4)     * 132 + n]);
            bf[ni][1] = __float_as_uint(Bs[(kk + t4 + 4) * 132 + n]);
        }
        #pragma unroll
        for (int mi = 0; mi < 2; mi++)
            #pragma unroll
            for (int ni = 0; ni < 4; ni++)
                MMA_TF32(acc3[mi][ni], af[mi][0], af[mi][1], af[mi][2],
                         af[mi][3], bf[ni][0], bf[ni][1]);
    }
    #pragma unroll
    for (int mi = 0; mi < 2; mi++) {
        #pragma unroll
        for (int ni = 0; ni < 4; ni++) {
            int pb = wM * 32 + mi * 16;
            int nb = wN * 32 + ni * 8 + 2 * t4;
            size_t base = (size_t)ci * (HEADDIM * DSTATE);
            *(float2*)(sinc + base + (pb + g)     * DSTATE + nb) =
                make_float2(acc3[mi][ni][0], acc3[mi][ni][1]);
            *(float2*)(sinc + base + (pb + g + 8) * DSTATE + nb) =
                make_float2(acc3[mi][ni][2], acc3[mi][ni][3]);
        }
    }
}

// ---------------------------------------------------------------------------
// Inter-chunk sequential recurrence: 64 CTAs (b,h), 256 threads, 64 steps.
// ---------------------------------------------------------------------------
__global__ __launch_bounds__(256)
void seq_kernel(const float* __restrict__ sinc,
                const float* __restrict__ cdec,
                float* __restrict__ state0)
{
    int bh = blockIdx.x;              // b*32 + h
    int b = bh >> 5, h = bh & 31;
    int tid = threadIdx.x;

    float st[32];
    #pragma unroll
    for (int j = 0; j < 32; j++) st[j] = 0.f;

    for (int k = 0; k < NCHUNK; k++) {
        int ci = b * (NHEADS * NCHUNK) + h * NCHUNK + k;
        float cd = cdec[ci];
        size_t base = (size_t)ci * (HEADDIM * DSTATE);
        #pragma unroll
        for (int j = 0; j < 32; j++) {
            size_t e = base + (size_t)j * 256 + tid;
            state0[e] = st[j];
            st[j] = fmaf(st[j], cd, sinc[e]);
        }
    }
}

// ---------------------------------------------------------------------------
// Apply inter-chunk state: y[t][p] += e^{A S_t} * sum_n C[t][n] state0[p][n]
// ---------------------------------------------------------------------------
#define AP_SMEM ((64*132 + 128*68 + 64) * 4)

__global__ __launch_bounds__(256)
void apply_kernel(const float* __restrict__ convout,
                  const float* __restrict__ state0,
                  const float* __restrict__ etbuf,
                  float* __restrict__ y)
{
    extern __shared__ float sm[];
    float* Cs  = sm;                  // [64][132]
    float* S0s = Cs + 64 * 132;       // [128][68]  [n][p]
    float* set = S0s + 128 * 68;      // 64

    const int ci    = blockIdx.x;
    const int chunk = ci & (NCHUNK - 1);
    const int h     = (ci >> 6) & (NHEADS - 1);
    const int b     = ci >> 11;
    const long r0   = (long)b * SEQLEN + chunk * T_CH;
    const int tid   = threadIdx.x;
    const int warp  = tid >> 5;
    const int lane  = tid & 31;
    const int g     = lane >> 2;
    const int t4    = lane & 3;
    const int wM    = warp >> 2;
    const int wN    = warp & 3;

    #pragma unroll
    for (int j = 0; j < 8; j++) {
        int idx = j * 256 + tid;
        int t = idx >> 5, q = idx & 31;
        float4 v = *(const float4*)(convout + (r0 + t) * CONVDIM + DINNER + DSTATE + q * 4);
        float* d = &Cs[t * 132 + q * 4];
        d[0] = tfr(v.x); d[1] = tfr(v.y); d[2] = tfr(v.z); d[3] = tfr(v.w);
    }
    {
        size_t base = (size_t)ci * (HEADDIM * DSTATE);
        #pragma unroll
        for (int j = 0; j < 32; j++) {
            int idx = j * 256 + tid;
            int p = idx >> 7, n = idx & 127;
            S0s[n * 68 + p] = tfr(state0[base + idx]);
        }
    }
    if (tid < 64) set[tid] = etbuf[(size_t)ci * T_CH + tid];
    __syncthreads();

    float acc[2][2][4];
    #pragma unroll
    for (int mi = 0; mi < 2; mi++)
        #pragma unroll
        for (int ni = 0; ni < 2; ni++)
            #pragma unroll
            for (int r = 0; r < 4; r++) acc[mi][ni][r] = 0.f;

    #pragma unroll
    for (int ks = 0; ks < 16; ks++) {
        const int kk = ks * 8;
        uint32_t af[2][4], bf[2][2];
        #pragma unroll
        for (int mi = 0; mi < 2; mi++) {
            int m = wM * 32 + mi * 16;
            af[mi][0] = __float_as_uint(Cs[(m + g)     * 132 + kk + t4]);
            af[mi][1] = __float_as_uint(Cs[(m + g + 8) * 132 + kk + t4]);
            af[mi][2] = __float_as_uint(Cs[(m + g)     * 132 + kk + t4 + 4]);
            af[mi][3] = __float_as_uint(Cs[(m + g + 8) * 132 + kk + t4 + 4]);
        }
        #pragma unroll
        for (int ni = 0; ni < 2; ni++) {
            int p = wN * 16 + ni * 8 + g;
            bf[ni][0] = __float_as_uint(S0s[(kk + t4)     * 68 + p]);
            bf[ni][1] = __float_as_uint(S0s[(kk + t4 + 4) * 68 + p]);
        }
        #pragma unroll
        for (int mi = 0; mi < 2; mi++)
            #pragma unroll
            for (int ni = 0; ni < 2; ni++)
                MMA_TF32(acc[mi][ni], af[mi][0], af[mi][1], af[mi][2],
                         af[mi][3], bf[ni][0], bf[ni][1]);
    }

    #pragma unroll
    for (int mi = 0; mi < 2; mi++) {
        #pragma unroll
        for (int ni = 0; ni < 2; ni++) {
            int tb = wM * 32 + mi * 16;
            int pb = wN * 16 + ni * 8 + 2 * t4;
            int t0 = tb + g, t1 = tb + g + 8;
            float e0 = set[t0], e1 = set[t1];
            float2* a0 = (float2*)(y + (r0 + t0) * DINNER + h * HEADDIM + pb);
            float2* a1 = (float2*)(y + (r0 + t1) * DINNER + h * HEADDIM + pb);
            float2 v0 = *a0, v1 = *a1;
            v0.x += e0 * acc[mi][ni][0]; v0.y += e0 * acc[mi][ni][1];
            v1.x += e1 * acc[mi][ni][2]; v1.y += e1 * acc[mi][ni][3];
            *a0 = v0; *a1 = v1;
        }
    }
}

// ---------------------------------------------------------------------------
// Gated RMSNorm in place on y; output tf32-rounded (feeds out_proj A).
// ---------------------------------------------------------------------------
__global__ __launch_bounds__(256)
void gated_rmsnorm_kernel(float* __restrict__ y,
                          const float* __restrict__ zxbcdt,
                          const float* __restrict__ norm_w)
{
    long r = blockIdx.x;
    int tid = threadIdx.x;
    float* yr = y + r * DINNER;
    const float* zr = zxbcdt + r * DINPROJ;

    float vals[8];
    float ss = 0.f;
    #pragma unroll
    for (int i = 0; i < 8; i++) {
        int c = tid + i * 256;
        float z  = zr[c];
        float gv = yr[c] * (z / (1.f + expf(-z)));
        vals[i] = gv;
        ss = fmaf(gv, gv, ss);
    }

    __shared__ float sred[256];
    sred[tid] = ss;
    __syncthreads();
    #pragma unroll
    for (int off = 128; off > 0; off >>= 1) {
        if (tid < off) sred[tid] += sred[tid + off];
        __syncthreads();
    }
    float scale = rsqrtf(sred[0] / (float)DINNER + 1e-5f);

    #pragma unroll
    for (int i = 0; i < 8; i++) {
        int c = tid + i * 256;
        yr[c] = tfr(vals[i] * scale * norm_w[c]);
    }
}

// ---------------------------------------------------------------------------
// Launch. Inputs: x, in_proj_w, conv_w, conv_b, norm_w, out_proj_w,
//                 dt_bias, A_log, D
// ---------------------------------------------------------------------------
extern "C" void kernel_launch(void* const* d_in, const int* in_sizes, int n_in,
                              void* d_out, int out_size)
{
    const float* x          = (const float*)d_in[0];
    const float* in_proj_w  = (const float*)d_in[1];
    const float* conv_w     = (const float*)d_in[2];
    const float* conv_b     = (const float*)d_in[3];
    const float* norm_w     = (const float*)d_in[4];
    const float* out_proj_w = (const float*)d_in[5];
    const float* dt_bias    = (const float*)d_in[6];
    const float* A_log      = (const float*)d_in[7];
    const float* Dparam     = (const float*)d_in[8];
    float* out = (float*)d_out;

    float *zxbcdt, *convbuf, *ybuf, *xtf, *w1tf, *w2tf, *dtb;
    float *sincb, *state0b, *etb, *cdecb;
    cudaGetSymbolAddress((void**)&zxbcdt,  g_zxbcdt);
    cudaGetSymbolAddress((void**)&convbuf, g_conv);
    cudaGetSymbolAddress((void**)&ybuf,    g_y);
    cudaGetSymbolAddress((void**)&xtf,     g_xtf);
    cudaGetSymbolAddress((void**)&w1tf,    g_w1tf);
    cudaGetSymbolAddress((void**)&w2tf,    g_w2tf);
    cudaGetSymbolAddress((void**)&dtb,     g_dt);
    cudaGetSymbolAddress((void**)&sincb,   g_sinc);
    cudaGetSymbolAddress((void**)&state0b, g_state0);
    cudaGetSymbolAddress((void**)&etb,     g_et);
    cudaGetSymbolAddress((void**)&cdecb,   g_cdec);

    cudaFuncSetAttribute(tf32_gemm_kernel,
                         cudaFuncAttributeMaxDynamicSharedMemorySize, GEMM_SMEM);
    cudaFuncSetAttribute(chunk_kernel,
                         cudaFuncAttributeMaxDynamicSharedMemorySize, CH_SMEM);
    cudaFuncSetAttribute(apply_kernel,
                         cudaFuncAttributeMaxDynamicSharedMemorySize, AP_SMEM);

    // 0) tf32 rounding pre-passes
    {
        long n4;
        n4 = (long)ROWS * DMODEL / 4;
        cvt_tf32_kernel<<<(unsigned)((n4 + 255) / 256), 256>>>(x, xtf, n4);
        n4 = (long)DMODEL * DINPROJ / 4;
        cvt_tf32_kernel<<<(unsigned)((n4 + 255) / 256), 256>>>(in_proj_w, w1tf, n4);
        n4 = (long)DINNER * DMODEL / 4;
        cvt_tf32_kernel<<<(unsigned)((n4 + 255) / 256), 256>>>(out_proj_w, w2tf, n4);
    }

    // 1) in_proj
    {
        dim3 grid((DINPROJ + 127) / 128, ROWS / 128);
        tf32_gemm_kernel<<<grid, 256, GEMM_SMEM>>>(xtf, w1tf, zxbcdt,
                                                   ROWS, DINPROJ, DMODEL);
    }

    // 2) conv + silu
    {
        long total = (long)ROWS * CONVDIM;
        conv_silu_kernel<<<(unsigned)((total + 255) / 256), 256>>>(
            zxbcdt, conv_w, conv_b, convbuf);
    }

    // 3) dt precompute
    {
        long total = (long)ROWS * NHEADS;
        dt_kernel<<<(unsigned)((total + 255) / 256), 256>>>(zxbcdt, dt_bias, dtb);
    }

    // 4) chunked scan: intra-chunk + state increments
    chunk_kernel<<<NCTA_CH, 256, CH_SMEM>>>(convbuf, dtb, A_log, Dparam,
                                            ybuf, sincb, etb, cdecb);

    // 5) inter-chunk recurrence
    seq_kernel<<<BATCH * NHEADS, 256>>>(sincb, cdecb, state0b);

    // 6) apply chunk-start states to y
    apply_kernel<<<NCTA_CH, 256, AP_SMEM>>>(convbuf, state0b, etb, ybuf);

    // 7) gated RMSNorm
    gated_rmsnorm_kernel<<<ROWS, 256>>>(ybuf, zxbcdt, norm_w);

    // 8) out_proj
    {
        dim3 grid(DMODEL / 128, ROWS / 128);
        tf32_gemm_kernel<<<grid, 256, GEMM_SMEM>>>(ybuf, w2tf, out,
                                                   ROWS, DMODEL, DINNER);
    }
}